// round 1
// baseline (speedup 1.0000x reference)
#include <cuda_runtime.h>

#define D_MODEL 1024
#define NUM_HEADS 16
#define BATCH 2
#define SEQ 2048
#define DK 64
#define M_TOT (BATCH*SEQ)   // 4096

// Scratch (allocation-free: __device__ globals)
__device__ float g_Q[(size_t)BATCH*NUM_HEADS*SEQ*DK];
__device__ float g_K[(size_t)BATCH*NUM_HEADS*SEQ*DK];
__device__ float g_V[(size_t)BATCH*NUM_HEADS*SEQ*DK];
__device__ float g_attn[(size_t)M_TOT*D_MODEL];

// ---------------- SGEMM tiles ----------------
#define BM 128
#define BN 128
#define BK 16
#define SPAD 132   // padded row stride (floats), keeps float4 alignment, reduces bank conflicts

// Fused QKV projection: Y = X @ W + b  for W in {Wq,Wk,Wv} (blockIdx.z selects),
// epilogue scatters to head-major [B,H,S,dk].
__global__ __launch_bounds__(256) void qkv_gemm(
    const float* __restrict__ X,
    const float* __restrict__ Wq, const float* __restrict__ bq,
    const float* __restrict__ Wk, const float* __restrict__ bk,
    const float* __restrict__ Wv, const float* __restrict__ bv)
{
    __shared__ __align__(16) float As[BK][SPAD];
    __shared__ __align__(16) float Bs[BK][SPAD];

    const float* W; const float* bias; float* dst;
    if (blockIdx.z == 0)      { W = Wq; bias = bq; dst = g_Q; }
    else if (blockIdx.z == 1) { W = Wk; bias = bk; dst = g_K; }
    else                      { W = Wv; bias = bv; dst = g_V; }

    const int K = D_MODEL, N = D_MODEL;
    const int tid = threadIdx.x;
    const int bx = blockIdx.x, by = blockIdx.y;
    const int tx = tid & 15, ty = tid >> 4;

    float acc[8][8];
    #pragma unroll
    for (int i = 0; i < 8; i++)
        #pragma unroll
        for (int j = 0; j < 8; j++) acc[i][j] = 0.f;

    const int ar = tid >> 2, ac4 = tid & 3;   // A-tile loader coords
    const int brk = tid >> 5, bc = tid & 31;  // B-tile loader coords

    for (int k0 = 0; k0 < K; k0 += BK) {
        #pragma unroll
        for (int rr = 0; rr < 2; rr++) {
            int row = ar + rr*64;
            float4 av = *(const float4*)&X[(size_t)(by*BM + row)*K + k0 + ac4*4];
            As[ac4*4+0][row] = av.x; As[ac4*4+1][row] = av.y;
            As[ac4*4+2][row] = av.z; As[ac4*4+3][row] = av.w;
        }
        #pragma unroll
        for (int rr = 0; rr < 2; rr++) {
            int rowk = brk + rr*8;
            *(float4*)&Bs[rowk][bc*4] =
                *(const float4*)&W[(size_t)(k0+rowk)*N + bx*BN + bc*4];
        }
        __syncthreads();
        #pragma unroll
        for (int kk = 0; kk < BK; kk++) {
            float a[8], b[8];
            *(float4*)&a[0] = *(const float4*)&As[kk][ty*8];
            *(float4*)&a[4] = *(const float4*)&As[kk][ty*8+4];
            *(float4*)&b[0] = *(const float4*)&Bs[kk][tx*8];
            *(float4*)&b[4] = *(const float4*)&Bs[kk][tx*8+4];
            #pragma unroll
            for (int i = 0; i < 8; i++)
                #pragma unroll
                for (int j = 0; j < 8; j++)
                    acc[i][j] += a[i]*b[j];
        }
        __syncthreads();
    }

    // Epilogue: scatter to [B,H,S,dk]
    #pragma unroll
    for (int j = 0; j < 8; j++) {
        int gn = bx*BN + tx*8 + j;
        float bb = bias[gn];
        int h = gn >> 6, d = gn & 63;
        #pragma unroll
        for (int i = 0; i < 8; i++) {
            int gm = by*BM + ty*8 + i;
            int bat = gm >> 11, s = gm & 2047;
            dst[((((size_t)bat*NUM_HEADS + h)*SEQ + s) << 6) + d] = acc[i][j] + bb;
        }
    }
}

// Output projection: out = g_attn @ Wo + bo (plain row-major epilogue)
__global__ __launch_bounds__(256) void out_gemm(
    const float* __restrict__ Wo, const float* __restrict__ bo,
    float* __restrict__ out)
{
    __shared__ __align__(16) float As[BK][SPAD];
    __shared__ __align__(16) float Bs[BK][SPAD];

    const int K = D_MODEL, N = D_MODEL;
    const int tid = threadIdx.x;
    const int bx = blockIdx.x, by = blockIdx.y;
    const int tx = tid & 15, ty = tid >> 4;

    float acc[8][8];
    #pragma unroll
    for (int i = 0; i < 8; i++)
        #pragma unroll
        for (int j = 0; j < 8; j++) acc[i][j] = 0.f;

    const int ar = tid >> 2, ac4 = tid & 3;
    const int brk = tid >> 5, bc = tid & 31;

    for (int k0 = 0; k0 < K; k0 += BK) {
        #pragma unroll
        for (int rr = 0; rr < 2; rr++) {
            int row = ar + rr*64;
            float4 av = *(const float4*)&g_attn[(size_t)(by*BM + row)*K + k0 + ac4*4];
            As[ac4*4+0][row] = av.x; As[ac4*4+1][row] = av.y;
            As[ac4*4+2][row] = av.z; As[ac4*4+3][row] = av.w;
        }
        #pragma unroll
        for (int rr = 0; rr < 2; rr++) {
            int rowk = brk + rr*8;
            *(float4*)&Bs[rowk][bc*4] =
                *(const float4*)&Wo[(size_t)(k0+rowk)*N + bx*BN + bc*4];
        }
        __syncthreads();
        #pragma unroll
        for (int kk = 0; kk < BK; kk++) {
            float a[8], b[8];
            *(float4*)&a[0] = *(const float4*)&As[kk][ty*8];
            *(float4*)&a[4] = *(const float4*)&As[kk][ty*8+4];
            *(float4*)&b[0] = *(const float4*)&Bs[kk][tx*8];
            *(float4*)&b[4] = *(const float4*)&Bs[kk][tx*8+4];
            #pragma unroll
            for (int i = 0; i < 8; i++)
                #pragma unroll
                for (int j = 0; j < 8; j++)
                    acc[i][j] += a[i]*b[j];
        }
        __syncthreads();
    }

    #pragma unroll
    for (int j = 0; j < 8; j++) {
        int gn = bx*BN + tx*8 + j;
        float bb = bo[gn];
        #pragma unroll
        for (int i = 0; i < 8; i++) {
            int gm = by*BM + ty*8 + i;
            out[(size_t)gm*N + gn] = acc[i][j] + bb;
        }
    }
}

// ---------------- Flash attention ----------------
// Block: 128 threads = 64 queries x 2 dim-halves (32 dims each).
// Online softmax with per-tile rescale; K/V tiles (32 keys) staged in smem.
__global__ __launch_bounds__(128) void attn_kernel()
{
    __shared__ __align__(16) float Ks[32][64];
    __shared__ __align__(16) float Vs[32][64];

    const int b = blockIdx.z, h = blockIdx.y;
    const int tid = threadIdx.x;
    const int ql = tid >> 1, half = tid & 1;
    const int q = blockIdx.x * 64 + ql;

    const size_t headoff = ((size_t)(b*NUM_HEADS + h)) * SEQ * DK;
    const float* Qp = g_Q + headoff + (size_t)q*DK + half*32;

    float qv[32];
    #pragma unroll
    for (int i = 0; i < 8; i++) {
        float4 t = ((const float4*)Qp)[i];
        qv[4*i+0] = t.x*0.125f; qv[4*i+1] = t.y*0.125f;
        qv[4*i+2] = t.z*0.125f; qv[4*i+3] = t.w*0.125f;
    }

    float acc[32];
    #pragma unroll
    for (int i = 0; i < 32; i++) acc[i] = 0.f;
    float mx = -1e30f, l = 0.f;

    const float4* Kg = (const float4*)(g_K + headoff);
    const float4* Vg = (const float4*)(g_V + headoff);
    float4* Kd = (float4*)&Ks[0][0];
    float4* Vd = (float4*)&Vs[0][0];

    for (int kt = 0; kt < SEQ/32; kt++) {
        #pragma unroll
        for (int i = 0; i < 4; i++) {
            Kd[tid + i*128] = Kg[(size_t)kt*512 + tid + i*128];
            Vd[tid + i*128] = Vg[(size_t)kt*512 + tid + i*128];
        }
        __syncthreads();

        float sc[32];
        #pragma unroll
        for (int j = 0; j < 32; j++) {
            const float4* kr = (const float4*)&Ks[j][half*32];
            float s = 0.f;
            #pragma unroll
            for (int d4 = 0; d4 < 8; d4++) {
                float4 kk = kr[d4];
                s += qv[4*d4+0]*kk.x + qv[4*d4+1]*kk.y
                   + qv[4*d4+2]*kk.z + qv[4*d4+3]*kk.w;
            }
            s += __shfl_xor_sync(0xffffffffu, s, 1);  // combine the two dim-halves
            sc[j] = s;
        }

        float tmax = mx;
        #pragma unroll
        for (int j = 0; j < 32; j++) tmax = fmaxf(tmax, sc[j]);
        float corr = __expf(mx - tmax);
        mx = tmax;
        l *= corr;
        #pragma unroll
        for (int i = 0; i < 32; i++) acc[i] *= corr;

        #pragma unroll
        for (int j = 0; j < 32; j++) {
            float p = __expf(sc[j] - mx);
            l += p;
            const float4* vr = (const float4*)&Vs[j][half*32];
            #pragma unroll
            for (int d4 = 0; d4 < 8; d4++) {
                float4 vv = vr[d4];
                acc[4*d4+0] += p*vv.x; acc[4*d4+1] += p*vv.y;
                acc[4*d4+2] += p*vv.z; acc[4*d4+3] += p*vv.w;
            }
        }
        __syncthreads();
    }

    float inv = 1.f / l;
    float* Op = g_attn + ((size_t)(b*SEQ + q))*D_MODEL + h*DK + half*32;
    #pragma unroll
    for (int i = 0; i < 8; i++) {
        float4 o;
        o.x = acc[4*i+0]*inv; o.y = acc[4*i+1]*inv;
        o.z = acc[4*i+2]*inv; o.w = acc[4*i+3]*inv;
        ((float4*)Op)[i] = o;
    }
}

extern "C" void kernel_launch(void* const* d_in, const int* in_sizes, int n_in,
                              void* d_out, int out_size)
{
    const float* X  = (const float*)d_in[0];
    const float* Wq = (const float*)d_in[1];
    const float* bq = (const float*)d_in[2];
    const float* Wk = (const float*)d_in[3];
    const float* bk = (const float*)d_in[4];
    const float* Wv = (const float*)d_in[5];
    const float* bv = (const float*)d_in[6];
    const float* Wo = (const float*)d_in[7];
    const float* bo = (const float*)d_in[8];
    float* out = (float*)d_out;

    dim3 gq(D_MODEL/BN, M_TOT/BM, 3);
    qkv_gemm<<<gq, 256>>>(X, Wq, bq, Wk, bk, Wv, bv);

    dim3 ga(SEQ/64, NUM_HEADS, BATCH);
    attn_kernel<<<ga, 128>>>();

    dim3 go(D_MODEL/BN, M_TOT/BM);
    out_gemm<<<go, 256>>>(Wo, bo, out);
}

// round 2
// speedup vs baseline: 1.3548x; 1.3548x over previous
#include <cuda_runtime.h>

#define D_MODEL 1024
#define NUM_HEADS 16
#define BATCH 2
#define SEQ 2048
#define DK 64
#define M_TOT (BATCH*SEQ)   // 4096

typedef unsigned long long ull;
struct __align__(16) ULL2 { ull x, y; };

__device__ __forceinline__ void fma2(ull& d, ull a, ull b) {
    asm("fma.rn.f32x2 %0, %1, %2, %0;" : "+l"(d) : "l"(a), "l"(b));
}
__device__ __forceinline__ ull pack2(float x, float y) {
    ull r; asm("mov.b64 %0, {%1, %2};" : "=l"(r) : "f"(x), "f"(y)); return r;
}
__device__ __forceinline__ void mul2(ull& d, ull a, ull b) {
    asm("mul.rn.f32x2 %0, %1, %2;" : "=l"(d) : "l"(a), "l"(b));
}
__device__ __forceinline__ void add2(ull& d, ull a, ull b) {
    asm("add.rn.f32x2 %0, %1, %2;" : "=l"(d) : "l"(a), "l"(b));
}
__device__ __forceinline__ float2 unpack2(ull v) {
    float2 f; asm("mov.b64 {%0, %1}, %2;" : "=f"(f.x), "=f"(f.y) : "l"(v)); return f;
}

// Scratch (allocation-free: __device__ globals)
__device__ float g_Q[(size_t)BATCH*NUM_HEADS*SEQ*DK];
__device__ float g_K[(size_t)BATCH*NUM_HEADS*SEQ*DK];
__device__ float g_V[(size_t)BATCH*NUM_HEADS*SEQ*DK];
__device__ float g_attn[(size_t)M_TOT*D_MODEL];

// ---------------- SGEMM tiles ----------------
#define BM 128
#define BN 128
#define BK 16
#define SPAD 132
#define ABUF (BK*SPAD)

// Shared GEMM body: 128x128 tile, 256 threads, 8x8 per thread, f32x2 math,
// double-buffered smem with register prefetch.
__device__ __forceinline__ void gemm_body(
    const float* __restrict__ A, const float* __restrict__ W,
    float* As, float* Bs, ull acc2[8][4])
{
    const int K = D_MODEL, N = D_MODEL;
    const int tid = threadIdx.x;
    const int tx = tid & 15, ty = tid >> 4;
    const int ar = tid >> 2, ac4 = tid & 3;
    const int brk = tid >> 5, bc = tid & 31;
    const int bx = blockIdx.x, by = blockIdx.y;

    float4 pa[2], pb[2];
    #pragma unroll
    for (int rr = 0; rr < 2; rr++)
        pa[rr] = *(const float4*)&A[(size_t)(by*BM + ar + rr*64)*K + ac4*4];
    #pragma unroll
    for (int rr = 0; rr < 2; rr++)
        pb[rr] = *(const float4*)&W[(size_t)(brk + rr*8)*N + bx*BN + bc*4];

    int buf = 0;
    for (int k0 = 0; k0 < K; k0 += BK) {
        // store prefetched tile into current buffer
        {
            float* dstA = As + buf*ABUF;
            #pragma unroll
            for (int rr = 0; rr < 2; rr++) {
                int row = ar + rr*64;
                dstA[(ac4*4+0)*SPAD + row] = pa[rr].x;
                dstA[(ac4*4+1)*SPAD + row] = pa[rr].y;
                dstA[(ac4*4+2)*SPAD + row] = pa[rr].z;
                dstA[(ac4*4+3)*SPAD + row] = pa[rr].w;
            }
            float* dstB = Bs + buf*ABUF;
            #pragma unroll
            for (int rr = 0; rr < 2; rr++)
                *(float4*)&dstB[(brk+rr*8)*SPAD + bc*4] = pb[rr];
        }
        __syncthreads();

        if (k0 + BK < K) {
            #pragma unroll
            for (int rr = 0; rr < 2; rr++)
                pa[rr] = *(const float4*)&A[(size_t)(by*BM + ar + rr*64)*K + k0 + BK + ac4*4];
            #pragma unroll
            for (int rr = 0; rr < 2; rr++)
                pb[rr] = *(const float4*)&W[(size_t)(k0 + BK + brk + rr*8)*N + bx*BN + bc*4];
        }

        const float* Ab = As + buf*ABUF;
        const float* Bb = Bs + buf*ABUF;
        #pragma unroll
        for (int kk = 0; kk < BK; kk++) {
            float a[8];
            *(float4*)&a[0] = *(const float4*)&Ab[kk*SPAD + ty*8];
            *(float4*)&a[4] = *(const float4*)&Ab[kk*SPAD + ty*8 + 4];
            ULL2 b01 = *(const ULL2*)&Bb[kk*SPAD + tx*8];
            ULL2 b23 = *(const ULL2*)&Bb[kk*SPAD + tx*8 + 4];
            #pragma unroll
            for (int i = 0; i < 8; i++) {
                ull aa = pack2(a[i], a[i]);
                fma2(acc2[i][0], aa, b01.x);
                fma2(acc2[i][1], aa, b01.y);
                fma2(acc2[i][2], aa, b23.x);
                fma2(acc2[i][3], aa, b23.y);
            }
        }
        buf ^= 1;
    }
}

// Fused QKV projection: Y = X @ W + b, epilogue scatters to head-major [B,H,S,dk]
__global__ __launch_bounds__(256) void qkv_gemm(
    const float* __restrict__ X,
    const float* __restrict__ Wq, const float* __restrict__ bq,
    const float* __restrict__ Wk, const float* __restrict__ bk,
    const float* __restrict__ Wv, const float* __restrict__ bv)
{
    __shared__ __align__(16) float As[2*ABUF];
    __shared__ __align__(16) float Bs[2*ABUF];

    const float* W; const float* bias; float* dst;
    if (blockIdx.z == 0)      { W = Wq; bias = bq; dst = g_Q; }
    else if (blockIdx.z == 1) { W = Wk; bias = bk; dst = g_K; }
    else                      { W = Wv; bias = bv; dst = g_V; }

    ull acc2[8][4];
    #pragma unroll
    for (int i = 0; i < 8; i++)
        #pragma unroll
        for (int j = 0; j < 4; j++) acc2[i][j] = 0ULL;

    gemm_body(X, W, As, Bs, acc2);

    const int tid = threadIdx.x;
    const int tx = tid & 15, ty = tid >> 4;
    const int bx = blockIdx.x, by = blockIdx.y;

    #pragma unroll
    for (int j2 = 0; j2 < 4; j2++) {
        #pragma unroll
        for (int i = 0; i < 8; i++) {
            float2 v = unpack2(acc2[i][j2]);
            int gm = by*BM + ty*8 + i;
            int bat = gm >> 11, s = gm & 2047;
            #pragma unroll
            for (int e = 0; e < 2; e++) {
                int gn = bx*BN + tx*8 + j2*2 + e;
                int h = gn >> 6, d = gn & 63;
                float val = (e ? v.y : v.x) + bias[gn];
                dst[((((size_t)bat*NUM_HEADS + h)*SEQ + s) << 6) + d] = val;
            }
        }
    }
}

// Output projection: out = g_attn @ Wo + bo
__global__ __launch_bounds__(256) void out_gemm(
    const float* __restrict__ Wo, const float* __restrict__ bo,
    float* __restrict__ out)
{
    __shared__ __align__(16) float As[2*ABUF];
    __shared__ __align__(16) float Bs[2*ABUF];

    ull acc2[8][4];
    #pragma unroll
    for (int i = 0; i < 8; i++)
        #pragma unroll
        for (int j = 0; j < 4; j++) acc2[i][j] = 0ULL;

    gemm_body(g_attn, Wo, As, Bs, acc2);

    const int tid = threadIdx.x;
    const int tx = tid & 15, ty = tid >> 4;
    const int bx = blockIdx.x, by = blockIdx.y;
    const int N = D_MODEL;

    #pragma unroll
    for (int j2 = 0; j2 < 4; j2++) {
        #pragma unroll
        for (int i = 0; i < 8; i++) {
            float2 v = unpack2(acc2[i][j2]);
            int gm = by*BM + ty*8 + i;
            int gn = bx*BN + tx*8 + j2*2;
            out[(size_t)gm*N + gn]     = v.x + bo[gn];
            out[(size_t)gm*N + gn + 1] = v.y + bo[gn+1];
        }
    }
}

// ---------------- Flash attention ----------------
// 128 threads/block, 1 thread = 1 full query (dk=64 in 32 f32x2 regs).
// No shuffles: dot product fully in-thread via packed FMA + horizontal add.
__global__ __launch_bounds__(128, 2) void attn_kernel()
{
    __shared__ __align__(16) float Ks[32][64];
    __shared__ __align__(16) float Vs[32][64];

    const int b = blockIdx.z, h = blockIdx.y;
    const int tid = threadIdx.x;
    const int q = blockIdx.x * 128 + tid;

    const size_t headoff = ((size_t)(b*NUM_HEADS + h)) * SEQ * DK;

    ull qv2[32];
    {
        const ULL2* Qp = (const ULL2*)(g_Q + headoff + (size_t)q*DK);
        ull scale = pack2(0.125f, 0.125f);
        #pragma unroll
        for (int i = 0; i < 16; i++) {
            ULL2 t = Qp[i];
            mul2(qv2[2*i],   t.x, scale);
            mul2(qv2[2*i+1], t.y, scale);
        }
    }

    ull acc2[32];
    #pragma unroll
    for (int i = 0; i < 32; i++) acc2[i] = 0ULL;
    float mx = -1e30f, l = 0.f;

    const float4* Kg = (const float4*)(g_K + headoff);
    const float4* Vg = (const float4*)(g_V + headoff);

    for (int kt = 0; kt < SEQ/32; kt++) {
        #pragma unroll
        for (int i = 0; i < 4; i++) {
            ((float4*)Ks)[tid + i*128] = Kg[(size_t)kt*512 + tid + i*128];
            ((float4*)Vs)[tid + i*128] = Vg[(size_t)kt*512 + tid + i*128];
        }
        __syncthreads();

        float sc[32];
        float tmax = mx;
        #pragma unroll 4
        for (int j = 0; j < 32; j++) {
            const ULL2* kr = (const ULL2*)&Ks[j][0];
            ull s0 = 0ULL, s1 = 0ULL, s2 = 0ULL, s3 = 0ULL;
            #pragma unroll
            for (int d = 0; d < 8; d++) {
                ULL2 ka = kr[2*d];
                ULL2 kb = kr[2*d+1];
                fma2(s0, qv2[4*d+0], ka.x);
                fma2(s1, qv2[4*d+1], ka.y);
                fma2(s2, qv2[4*d+2], kb.x);
                fma2(s3, qv2[4*d+3], kb.y);
            }
            add2(s0, s0, s1);
            add2(s2, s2, s3);
            add2(s0, s0, s2);
            float2 f = unpack2(s0);
            float s = f.x + f.y;
            sc[j] = s;
            tmax = fmaxf(tmax, s);
        }

        float corr = __expf(mx - tmax);
        mx = tmax;
        l *= corr;
        ull c2 = pack2(corr, corr);
        #pragma unroll
        for (int i = 0; i < 32; i++) mul2(acc2[i], acc2[i], c2);

        #pragma unroll 4
        for (int j = 0; j < 32; j++) {
            float p = __expf(sc[j] - mx);
            l += p;
            ull pp = pack2(p, p);
            const ULL2* vr = (const ULL2*)&Vs[j][0];
            #pragma unroll
            for (int d = 0; d < 16; d++) {
                ULL2 vv = vr[d];
                fma2(acc2[2*d],   pp, vv.x);
                fma2(acc2[2*d+1], pp, vv.y);
            }
        }
        __syncthreads();
    }

    float inv = 1.f / l;
    ull i2 = pack2(inv, inv);
    ULL2* Op = (ULL2*)(g_attn + ((size_t)(b*SEQ + q))*D_MODEL + h*DK);
    #pragma unroll
    for (int d = 0; d < 16; d++) {
        ULL2 o;
        mul2(o.x, acc2[2*d],   i2);
        mul2(o.y, acc2[2*d+1], i2);
        Op[d] = o;
    }
}

extern "C" void kernel_launch(void* const* d_in, const int* in_sizes, int n_in,
                              void* d_out, int out_size)
{
    const float* X  = (const float*)d_in[0];
    const float* Wq = (const float*)d_in[1];
    const float* bq = (const float*)d_in[2];
    const float* Wk = (const float*)d_in[3];
    const float* bk = (const float*)d_in[4];
    const float* Wv = (const float*)d_in[5];
    const float* bv = (const float*)d_in[6];
    const float* Wo = (const float*)d_in[7];
    const float* bo = (const float*)d_in[8];
    float* out = (float*)d_out;

    dim3 gq(D_MODEL/BN, M_TOT/BM, 3);
    qkv_gemm<<<gq, 256>>>(X, Wq, bq, Wk, bk, Wv, bv);

    dim3 ga(SEQ/128, NUM_HEADS, BATCH);
    attn_kernel<<<ga, 128>>>();

    dim3 go(D_MODEL/BN, M_TOT/BM);
    out_gemm<<<go, 256>>>(Wo, bo, out);
}

// round 3
// speedup vs baseline: 1.8284x; 1.3495x over previous
#include <cuda_runtime.h>
#include <cuda_bf16.h>

#define D_MODEL 1024
#define NUM_HEADS 16
#define BATCH 2
#define SEQ 2048
#define DK 64
#define M_TOT (BATCH*SEQ)   // 4096

typedef unsigned int uint;
typedef unsigned long long ull;
struct __align__(16) ULL2 { ull x, y; };

// ---- f32x2 helpers (attention) ----
__device__ __forceinline__ void fma2(ull& d, ull a, ull b) {
    asm("fma.rn.f32x2 %0, %1, %2, %0;" : "+l"(d) : "l"(a), "l"(b));
}
__device__ __forceinline__ ull pack2(float x, float y) {
    ull r; asm("mov.b64 %0, {%1, %2};" : "=l"(r) : "f"(x), "f"(y)); return r;
}
__device__ __forceinline__ void mul2(ull& d, ull a, ull b) {
    asm("mul.rn.f32x2 %0, %1, %2;" : "=l"(d) : "l"(a), "l"(b));
}
__device__ __forceinline__ void add2(ull& d, ull a, ull b) {
    asm("add.rn.f32x2 %0, %1, %2;" : "=l"(d) : "l"(a), "l"(b));
}
__device__ __forceinline__ float2 unpack2(ull v) {
    float2 f; asm("mov.b64 {%0, %1}, %2;" : "=f"(f.x), "=f"(f.y) : "l"(v)); return f;
}

// Scratch (allocation-free: __device__ globals)
__device__ float g_Q[(size_t)BATCH*NUM_HEADS*SEQ*DK];
__device__ float g_K[(size_t)BATCH*NUM_HEADS*SEQ*DK];
__device__ float g_V[(size_t)BATCH*NUM_HEADS*SEQ*DK];
__device__ float g_attn[(size_t)M_TOT*D_MODEL];

// ================= tensor-core GEMM (split-bf16, 3-pass) =================
#define BM 128
#define BN 128
#define BK 32
#define ASTR 40    // bf16 elements per A-smem row (32 + 8 pad) -> 80B stride, ldmatrix conflict-free
#define BSTR 136   // bf16 elements per B-smem row (128 + 8 pad) -> 272B stride, conflict-free
#define AH_OFF 0
#define AL_OFF (BM*ASTR)                 // 5120
#define BH_OFF (2*BM*ASTR)               // 10240
#define BL_OFF (2*BM*ASTR + BK*BSTR)     // 14592
#define BUF_ELEMS (2*BM*ASTR + 2*BK*BSTR) // 18944 bf16
#define GEMM_SMEM_BYTES (2*BUF_ELEMS*2)   // 75776 B

__device__ __forceinline__ uint smaddr(const void* p) {
    return (uint)__cvta_generic_to_shared(p);
}
__device__ __forceinline__ void ldsm4(uint addr, uint& r0, uint& r1, uint& r2, uint& r3) {
    asm volatile("ldmatrix.sync.aligned.m8n8.x4.shared.b16 {%0,%1,%2,%3}, [%4];"
        : "=r"(r0), "=r"(r1), "=r"(r2), "=r"(r3) : "r"(addr));
}
__device__ __forceinline__ void ldsm4t(uint addr, uint& r0, uint& r1, uint& r2, uint& r3) {
    asm volatile("ldmatrix.sync.aligned.m8n8.x4.trans.shared.b16 {%0,%1,%2,%3}, [%4];"
        : "=r"(r0), "=r"(r1), "=r"(r2), "=r"(r3) : "r"(addr));
}
__device__ __forceinline__ void mma16816(float c[4], const uint a[4], const uint b[2]) {
    asm volatile("mma.sync.aligned.m16n8k16.row.col.f32.bf16.bf16.f32 "
        "{%0,%1,%2,%3}, {%4,%5,%6,%7}, {%8,%9}, {%0,%1,%2,%3};"
        : "+f"(c[0]), "+f"(c[1]), "+f"(c[2]), "+f"(c[3])
        : "r"(a[0]), "r"(a[1]), "r"(a[2]), "r"(a[3]), "r"(b[0]), "r"(b[1]));
}

// split fp32x4 into bf16 hi/lo x4 and store (8B stores)
__device__ __forceinline__ void split_store4(__nv_bfloat16* hi, __nv_bfloat16* lo, float4 v) {
    __nv_bfloat162 h01 = __floats2bfloat162_rn(v.x, v.y);
    __nv_bfloat162 h23 = __floats2bfloat162_rn(v.z, v.w);
    float2 f01 = __bfloat1622float2(h01);
    float2 f23 = __bfloat1622float2(h23);
    __nv_bfloat162 l01 = __floats2bfloat162_rn(v.x - f01.x, v.y - f01.y);
    __nv_bfloat162 l23 = __floats2bfloat162_rn(v.z - f23.x, v.w - f23.y);
    uint2 hv, lv;
    hv.x = *(uint*)&h01; hv.y = *(uint*)&h23;
    lv.x = *(uint*)&l01; lv.y = *(uint*)&l23;
    *(uint2*)hi = hv;
    *(uint2*)lo = lv;
}

// GEMM body: C[128x128] = A[128xK] @ W[KxN] tile, fp32-accurate via 3-pass split-bf16.
// 256 threads = 8 warps in 2(M) x 4(N); warp tile 64x32 = 4x4 mma tiles.
__device__ __forceinline__ void mma_gemm_body(
    const float* __restrict__ A, const float* __restrict__ W,
    __nv_bfloat16* sm, float C[4][4][4])
{
    const int K = D_MODEL, N = D_MODEL;
    const int tid = threadIdx.x;
    const int lane = tid & 31, w = tid >> 5;
    const int wm = (w >> 2) * 64, wn = (w & 3) * 32;
    const int bx = blockIdx.x, by = blockIdx.y;

    // loader coords
    const int a_row = tid >> 1, a_c0 = (tid & 1) * 16;
    const int b_r0 = tid >> 5, b_c = (tid & 31) * 4;

    // ldmatrix lane addressing
    const int lrow = lane & 15;
    const int lkoff = (lane >> 4) << 3;
    const int tg = lane >> 3;
    const int b_lrow = (tg & 1) * 8 + (lane & 7);
    const int b_lcol = (tg >> 1) * 8;

    float4 pa[4], pb[4];
    #pragma unroll
    for (int q = 0; q < 4; q++)
        pa[q] = *(const float4*)&A[(size_t)(by*BM + a_row)*K + a_c0 + 4*q];
    #pragma unroll
    for (int q = 0; q < 4; q++)
        pb[q] = *(const float4*)&W[(size_t)(b_r0 + 8*q)*N + bx*BN + b_c];

    int buf = 0;
    for (int k0 = 0; k0 < K; k0 += BK) {
        __nv_bfloat16* S = sm + buf*BUF_ELEMS;
        #pragma unroll
        for (int q = 0; q < 4; q++)
            split_store4(S + AH_OFF + a_row*ASTR + a_c0 + 4*q,
                         S + AL_OFF + a_row*ASTR + a_c0 + 4*q, pa[q]);
        #pragma unroll
        for (int q = 0; q < 4; q++)
            split_store4(S + BH_OFF + (b_r0 + 8*q)*BSTR + b_c,
                         S + BL_OFF + (b_r0 + 8*q)*BSTR + b_c, pb[q]);
        __syncthreads();

        if (k0 + BK < K) {
            #pragma unroll
            for (int q = 0; q < 4; q++)
                pa[q] = *(const float4*)&A[(size_t)(by*BM + a_row)*K + k0 + BK + a_c0 + 4*q];
            #pragma unroll
            for (int q = 0; q < 4; q++)
                pb[q] = *(const float4*)&W[(size_t)(k0 + BK + b_r0 + 8*q)*N + bx*BN + b_c];
        }

        #pragma unroll
        for (int ks = 0; ks < 2; ks++) {
            const int kk = ks * 16;
            uint ah[4][4], al[4][4], bh[4][2], bl[4][2];
            #pragma unroll
            for (int i = 0; i < 4; i++) {
                uint ad = smaddr(S + AH_OFF + (wm + i*16 + lrow)*ASTR + kk + lkoff);
                ldsm4(ad, ah[i][0], ah[i][1], ah[i][2], ah[i][3]);
                ldsm4(ad + AL_OFF*2, al[i][0], al[i][1], al[i][2], al[i][3]);
            }
            #pragma unroll
            for (int p = 0; p < 2; p++) {
                uint bd = smaddr(S + BH_OFF + (kk + b_lrow)*BSTR + wn + p*16 + b_lcol);
                ldsm4t(bd, bh[2*p][0], bh[2*p][1], bh[2*p+1][0], bh[2*p+1][1]);
                ldsm4t(bd + (BL_OFF - BH_OFF)*2,
                       bl[2*p][0], bl[2*p][1], bl[2*p+1][0], bl[2*p+1][1]);
            }
            #pragma unroll
            for (int i = 0; i < 4; i++)
                #pragma unroll
                for (int j = 0; j < 4; j++) {
                    mma16816(C[i][j], ah[i], bh[j]);   // hi*hi
                    mma16816(C[i][j], ah[i], bl[j]);   // hi*lo
                    mma16816(C[i][j], al[i], bh[j]);   // lo*hi
                }
        }
        __syncthreads();
        buf ^= 1;
    }
}

// QKV projection: Y = X @ W + b, scattered to head-major [B,H,S,dk]
__global__ __launch_bounds__(256) void qkv_gemm(
    const float* __restrict__ X,
    const float* __restrict__ Wq, const float* __restrict__ bq,
    const float* __restrict__ Wk, const float* __restrict__ bk,
    const float* __restrict__ Wv, const float* __restrict__ bv)
{
    extern __shared__ __align__(16) __nv_bfloat16 sm[];

    const float* W; const float* bias; float* dst;
    if (blockIdx.z == 0)      { W = Wq; bias = bq; dst = g_Q; }
    else if (blockIdx.z == 1) { W = Wk; bias = bk; dst = g_K; }
    else                      { W = Wv; bias = bv; dst = g_V; }

    float C[4][4][4];
    #pragma unroll
    for (int i = 0; i < 4; i++)
        #pragma unroll
        for (int j = 0; j < 4; j++)
            #pragma unroll
            for (int e = 0; e < 4; e++) C[i][j][e] = 0.f;

    mma_gemm_body(X, W, sm, C);

    const int tid = threadIdx.x;
    const int lane = tid & 31, w = tid >> 5;
    const int wm = (w >> 2) * 64, wn = (w & 3) * 32;
    const int bx = blockIdx.x, by = blockIdx.y;
    const int r = lane >> 2, c2 = (lane & 3) * 2;

    #pragma unroll
    for (int i = 0; i < 4; i++)
        #pragma unroll
        for (int j = 0; j < 4; j++) {
            int gn = bx*BN + wn + j*8 + c2;
            int h = gn >> 6, d = gn & 63;
            float b0 = bias[gn], b1 = bias[gn+1];
            #pragma unroll
            for (int rr = 0; rr < 2; rr++) {
                int gm = by*BM + wm + i*16 + r + rr*8;
                int bat = gm >> 11, s = gm & 2047;
                float2 v;
                v.x = C[i][j][rr*2+0] + b0;
                v.y = C[i][j][rr*2+1] + b1;
                *(float2*)&dst[((((size_t)bat*NUM_HEADS + h)*SEQ + s) << 6) + d] = v;
            }
        }
}

// Output projection: out = g_attn @ Wo + bo
__global__ __launch_bounds__(256) void out_gemm(
    const float* __restrict__ Wo, const float* __restrict__ bo,
    float* __restrict__ out)
{
    extern __shared__ __align__(16) __nv_bfloat16 sm[];

    float C[4][4][4];
    #pragma unroll
    for (int i = 0; i < 4; i++)
        #pragma unroll
        for (int j = 0; j < 4; j++)
            #pragma unroll
            for (int e = 0; e < 4; e++) C[i][j][e] = 0.f;

    mma_gemm_body(g_attn, Wo, sm, C);

    const int tid = threadIdx.x;
    const int lane = tid & 31, w = tid >> 5;
    const int wm = (w >> 2) * 64, wn = (w & 3) * 32;
    const int bx = blockIdx.x, by = blockIdx.y;
    const int r = lane >> 2, c2 = (lane & 3) * 2;
    const int N = D_MODEL;

    #pragma unroll
    for (int i = 0; i < 4; i++)
        #pragma unroll
        for (int j = 0; j < 4; j++) {
            int gn = bx*BN + wn + j*8 + c2;
            float b0 = bo[gn], b1 = bo[gn+1];
            #pragma unroll
            for (int rr = 0; rr < 2; rr++) {
                int gm = by*BM + wm + i*16 + r + rr*8;
                float2 v;
                v.x = C[i][j][rr*2+0] + b0;
                v.y = C[i][j][rr*2+1] + b1;
                *(float2*)&out[(size_t)gm*N + gn] = v;
            }
        }
}

// ---------------- Flash attention (unchanged from R2) ----------------
__global__ __launch_bounds__(128, 2) void attn_kernel()
{
    __shared__ __align__(16) float Ks[32][64];
    __shared__ __align__(16) float Vs[32][64];

    const int b = blockIdx.z, h = blockIdx.y;
    const int tid = threadIdx.x;
    const int q = blockIdx.x * 128 + tid;

    const size_t headoff = ((size_t)(b*NUM_HEADS + h)) * SEQ * DK;

    ull qv2[32];
    {
        const ULL2* Qp = (const ULL2*)(g_Q + headoff + (size_t)q*DK);
        ull scale = pack2(0.125f, 0.125f);
        #pragma unroll
        for (int i = 0; i < 16; i++) {
            ULL2 t = Qp[i];
            mul2(qv2[2*i],   t.x, scale);
            mul2(qv2[2*i+1], t.y, scale);
        }
    }

    ull acc2[32];
    #pragma unroll
    for (int i = 0; i < 32; i++) acc2[i] = 0ULL;
    float mx = -1e30f, l = 0.f;

    const float4* Kg = (const float4*)(g_K + headoff);
    const float4* Vg = (const float4*)(g_V + headoff);

    for (int kt = 0; kt < SEQ/32; kt++) {
        #pragma unroll
        for (int i = 0; i < 4; i++) {
            ((float4*)Ks)[tid + i*128] = Kg[(size_t)kt*512 + tid + i*128];
            ((float4*)Vs)[tid + i*128] = Vg[(size_t)kt*512 + tid + i*128];
        }
        __syncthreads();

        float sc[32];
        float tmax = mx;
        #pragma unroll 4
        for (int j = 0; j < 32; j++) {
            const ULL2* kr = (const ULL2*)&Ks[j][0];
            ull s0 = 0ULL, s1 = 0ULL, s2 = 0ULL, s3 = 0ULL;
            #pragma unroll
            for (int d = 0; d < 8; d++) {
                ULL2 ka = kr[2*d];
                ULL2 kb = kr[2*d+1];
                fma2(s0, qv2[4*d+0], ka.x);
                fma2(s1, qv2[4*d+1], ka.y);
                fma2(s2, qv2[4*d+2], kb.x);
                fma2(s3, qv2[4*d+3], kb.y);
            }
            add2(s0, s0, s1);
            add2(s2, s2, s3);
            add2(s0, s0, s2);
            float2 f = unpack2(s0);
            float s = f.x + f.y;
            sc[j] = s;
            tmax = fmaxf(tmax, s);
        }

        float corr = __expf(mx - tmax);
        mx = tmax;
        l *= corr;
        ull c2 = pack2(corr, corr);
        #pragma unroll
        for (int i = 0; i < 32; i++) mul2(acc2[i], acc2[i], c2);

        #pragma unroll 4
        for (int j = 0; j < 32; j++) {
            float p = __expf(sc[j] - mx);
            l += p;
            ull pp = pack2(p, p);
            const ULL2* vr = (const ULL2*)&Vs[j][0];
            #pragma unroll
            for (int d = 0; d < 16; d++) {
                ULL2 vv = vr[d];
                fma2(acc2[2*d],   pp, vv.x);
                fma2(acc2[2*d+1], pp, vv.y);
            }
        }
        __syncthreads();
    }

    float inv = 1.f / l;
    ull i2 = pack2(inv, inv);
    ULL2* Op = (ULL2*)(g_attn + ((size_t)(b*SEQ + q))*D_MODEL + h*DK);
    #pragma unroll
    for (int d = 0; d < 16; d++) {
        ULL2 o;
        mul2(o.x, acc2[2*d],   i2);
        mul2(o.y, acc2[2*d+1], i2);
        Op[d] = o;
    }
}

extern "C" void kernel_launch(void* const* d_in, const int* in_sizes, int n_in,
                              void* d_out, int out_size)
{
    const float* X  = (const float*)d_in[0];
    const float* Wq = (const float*)d_in[1];
    const float* bq = (const float*)d_in[2];
    const float* Wk = (const float*)d_in[3];
    const float* bk = (const float*)d_in[4];
    const float* Wv = (const float*)d_in[5];
    const float* bv = (const float*)d_in[6];
    const float* Wo = (const float*)d_in[7];
    const float* bo = (const float*)d_in[8];
    float* out = (float*)d_out;

    static int configured = 0;
    if (!configured) {
        cudaFuncSetAttribute(qkv_gemm, cudaFuncAttributeMaxDynamicSharedMemorySize, GEMM_SMEM_BYTES);
        cudaFuncSetAttribute(out_gemm, cudaFuncAttributeMaxDynamicSharedMemorySize, GEMM_SMEM_BYTES);
        configured = 1;
    }

    dim3 gq(D_MODEL/BN, M_TOT/BM, 3);
    qkv_gemm<<<gq, 256, GEMM_SMEM_BYTES>>>(X, Wq, bq, Wk, bk, Wv, bv);

    dim3 ga(SEQ/128, NUM_HEADS, BATCH);
    attn_kernel<<<ga, 128>>>();

    dim3 go(D_MODEL/BN, M_TOT/BM);
    out_gemm<<<go, 256, GEMM_SMEM_BYTES>>>(Wo, bo, out);
}

// round 4
// speedup vs baseline: 4.0430x; 2.2113x over previous
#include <cuda_runtime.h>
#include <cuda_bf16.h>

#define D_MODEL 1024
#define NUM_HEADS 16
#define BATCH 2
#define SEQ 2048
#define DK 64
#define M_TOT (BATCH*SEQ)   // 4096

typedef unsigned int uint;

// log2(e)/sqrt(dk) folded into stored Q
#define SCALE_Q 0.1803368801111244f

// Scratch (allocation-free: __device__ globals) — split bf16 hi/lo
#define QKV_ELEMS ((size_t)BATCH*NUM_HEADS*SEQ*DK)
__device__ __nv_bfloat16 g_Qh[QKV_ELEMS];
__device__ __nv_bfloat16 g_Ql[QKV_ELEMS];
__device__ __nv_bfloat16 g_Kh[QKV_ELEMS];
__device__ __nv_bfloat16 g_Kl[QKV_ELEMS];
__device__ __nv_bfloat16 g_Vh[QKV_ELEMS];
__device__ __nv_bfloat16 g_Vl[QKV_ELEMS];
__device__ float g_attn[(size_t)M_TOT*D_MODEL];

__device__ __forceinline__ uint smaddr(const void* p) {
    return (uint)__cvta_generic_to_shared(p);
}
__device__ __forceinline__ void ldsm4(uint addr, uint& r0, uint& r1, uint& r2, uint& r3) {
    asm volatile("ldmatrix.sync.aligned.m8n8.x4.shared.b16 {%0,%1,%2,%3}, [%4];"
        : "=r"(r0), "=r"(r1), "=r"(r2), "=r"(r3) : "r"(addr));
}
__device__ __forceinline__ void ldsm4t(uint addr, uint& r0, uint& r1, uint& r2, uint& r3) {
    asm volatile("ldmatrix.sync.aligned.m8n8.x4.trans.shared.b16 {%0,%1,%2,%3}, [%4];"
        : "=r"(r0), "=r"(r1), "=r"(r2), "=r"(r3) : "r"(addr));
}
__device__ __forceinline__ void mma16816(float c[4], const uint a[4], uint b0, uint b1) {
    asm volatile("mma.sync.aligned.m16n8k16.row.col.f32.bf16.bf16.f32 "
        "{%0,%1,%2,%3}, {%4,%5,%6,%7}, {%8,%9}, {%0,%1,%2,%3};"
        : "+f"(c[0]), "+f"(c[1]), "+f"(c[2]), "+f"(c[3])
        : "r"(a[0]), "r"(a[1]), "r"(a[2]), "r"(a[3]), "r"(b0), "r"(b1));
}
__device__ __forceinline__ float ex2(float x) {
    float y; asm("ex2.approx.f32 %0, %1;" : "=f"(y) : "f"(x)); return y;
}
// split fp32 pair -> bf16x2 hi + bf16x2 lo (as uints)
__device__ __forceinline__ void split2(float x, float y, uint& hv, uint& lv) {
    __nv_bfloat162 h = __floats2bfloat162_rn(x, y);
    float2 hf = __bfloat1622float2(h);
    __nv_bfloat162 l = __floats2bfloat162_rn(x - hf.x, y - hf.y);
    hv = *(uint*)&h; lv = *(uint*)&l;
}

// ================= tensor-core GEMM (split-bf16, 3-pass) =================
#define BM 128
#define BN 128
#define BK 32
#define ASTR 40
#define BSTR 136
#define AH_OFF 0
#define AL_OFF (BM*ASTR)
#define BH_OFF (2*BM*ASTR)
#define BL_OFF (2*BM*ASTR + BK*BSTR)
#define BUF_ELEMS (2*BM*ASTR + 2*BK*BSTR)
#define GEMM_SMEM_BYTES (2*BUF_ELEMS*2)

__device__ __forceinline__ void split_store4(__nv_bfloat16* hi, __nv_bfloat16* lo, float4 v) {
    uint2 hv, lv;
    split2(v.x, v.y, hv.x, lv.x);
    split2(v.z, v.w, hv.y, lv.y);
    *(uint2*)hi = hv;
    *(uint2*)lo = lv;
}

__device__ __forceinline__ void mma_gemm_body(
    const float* __restrict__ A, const float* __restrict__ W,
    __nv_bfloat16* sm, float C[4][4][4])
{
    const int K = D_MODEL, N = D_MODEL;
    const int tid = threadIdx.x;
    const int lane = tid & 31, w = tid >> 5;
    const int wm = (w >> 2) * 64, wn = (w & 3) * 32;
    const int bx = blockIdx.x, by = blockIdx.y;

    const int a_row = tid >> 1, a_c0 = (tid & 1) * 16;
    const int b_r0 = tid >> 5, b_c = (tid & 31) * 4;

    const int lrow = lane & 15;
    const int lkoff = (lane >> 4) << 3;
    const int tg = lane >> 3;
    const int b_lrow = (tg & 1) * 8 + (lane & 7);
    const int b_lcol = (tg >> 1) * 8;

    float4 pa[4], pb[4];
    #pragma unroll
    for (int q = 0; q < 4; q++)
        pa[q] = *(const float4*)&A[(size_t)(by*BM + a_row)*K + a_c0 + 4*q];
    #pragma unroll
    for (int q = 0; q < 4; q++)
        pb[q] = *(const float4*)&W[(size_t)(b_r0 + 8*q)*N + bx*BN + b_c];

    int buf = 0;
    for (int k0 = 0; k0 < K; k0 += BK) {
        __nv_bfloat16* S = sm + buf*BUF_ELEMS;
        #pragma unroll
        for (int q = 0; q < 4; q++)
            split_store4(S + AH_OFF + a_row*ASTR + a_c0 + 4*q,
                         S + AL_OFF + a_row*ASTR + a_c0 + 4*q, pa[q]);
        #pragma unroll
        for (int q = 0; q < 4; q++)
            split_store4(S + BH_OFF + (b_r0 + 8*q)*BSTR + b_c,
                         S + BL_OFF + (b_r0 + 8*q)*BSTR + b_c, pb[q]);
        __syncthreads();

        if (k0 + BK < K) {
            #pragma unroll
            for (int q = 0; q < 4; q++)
                pa[q] = *(const float4*)&A[(size_t)(by*BM + a_row)*K + k0 + BK + a_c0 + 4*q];
            #pragma unroll
            for (int q = 0; q < 4; q++)
                pb[q] = *(const float4*)&W[(size_t)(k0 + BK + b_r0 + 8*q)*N + bx*BN + b_c];
        }

        #pragma unroll
        for (int ks = 0; ks < 2; ks++) {
            const int kk = ks * 16;
            uint ah[4][4], al[4][4], bh[4][2], bl[4][2];
            #pragma unroll
            for (int i = 0; i < 4; i++) {
                uint ad = smaddr(S + AH_OFF + (wm + i*16 + lrow)*ASTR + kk + lkoff);
                ldsm4(ad, ah[i][0], ah[i][1], ah[i][2], ah[i][3]);
                ldsm4(ad + AL_OFF*2, al[i][0], al[i][1], al[i][2], al[i][3]);
            }
            #pragma unroll
            for (int p = 0; p < 2; p++) {
                uint bd = smaddr(S + BH_OFF + (kk + b_lrow)*BSTR + wn + p*16 + b_lcol);
                ldsm4t(bd, bh[2*p][0], bh[2*p][1], bh[2*p+1][0], bh[2*p+1][1]);
                ldsm4t(bd + (BL_OFF - BH_OFF)*2,
                       bl[2*p][0], bl[2*p][1], bl[2*p+1][0], bl[2*p+1][1]);
            }
            #pragma unroll
            for (int i = 0; i < 4; i++)
                #pragma unroll
                for (int j = 0; j < 4; j++) {
                    mma16816(C[i][j], ah[i], bh[j][0], bh[j][1]);
                    mma16816(C[i][j], ah[i], bl[j][0], bl[j][1]);
                    mma16816(C[i][j], al[i], bh[j][0], bh[j][1]);
                }
        }
        __syncthreads();
        buf ^= 1;
    }
}

// QKV projection -> split bf16 head-major [B,H,S,dk]; Q pre-scaled by SCALE_Q
__global__ __launch_bounds__(256) void qkv_gemm(
    const float* __restrict__ X,
    const float* __restrict__ Wq, const float* __restrict__ bq,
    const float* __restrict__ Wk, const float* __restrict__ bk,
    const float* __restrict__ Wv, const float* __restrict__ bv)
{
    extern __shared__ __align__(16) __nv_bfloat16 sm[];

    const float* W; const float* bias;
    __nv_bfloat16 *dsth, *dstl;
    float scale;
    if (blockIdx.z == 0)      { W = Wq; bias = bq; dsth = g_Qh; dstl = g_Ql; scale = SCALE_Q; }
    else if (blockIdx.z == 1) { W = Wk; bias = bk; dsth = g_Kh; dstl = g_Kl; scale = 1.f; }
    else                      { W = Wv; bias = bv; dsth = g_Vh; dstl = g_Vl; scale = 1.f; }

    float C[4][4][4];
    #pragma unroll
    for (int i = 0; i < 4; i++)
        #pragma unroll
        for (int j = 0; j < 4; j++)
            #pragma unroll
            for (int e = 0; e < 4; e++) C[i][j][e] = 0.f;

    mma_gemm_body(X, W, sm, C);

    const int tid = threadIdx.x;
    const int lane = tid & 31, w = tid >> 5;
    const int wm = (w >> 2) * 64, wn = (w & 3) * 32;
    const int bx = blockIdx.x, by = blockIdx.y;
    const int r = lane >> 2, c2 = (lane & 3) * 2;

    #pragma unroll
    for (int i = 0; i < 4; i++)
        #pragma unroll
        for (int j = 0; j < 4; j++) {
            int gn = bx*BN + wn + j*8 + c2;
            int h = gn >> 6, d = gn & 63;
            float b0 = bias[gn], b1 = bias[gn+1];
            #pragma unroll
            for (int rr = 0; rr < 2; rr++) {
                int gm = by*BM + wm + i*16 + r + rr*8;
                int bat = gm >> 11, s = gm & 2047;
                float vx = (C[i][j][rr*2+0] + b0) * scale;
                float vy = (C[i][j][rr*2+1] + b1) * scale;
                uint hv, lv;
                split2(vx, vy, hv, lv);
                size_t idx = ((((size_t)bat*NUM_HEADS + h)*SEQ + s) << 6) + d;
                *(uint*)&dsth[idx] = hv;
                *(uint*)&dstl[idx] = lv;
            }
        }
}

// Output projection: out = g_attn @ Wo + bo
__global__ __launch_bounds__(256) void out_gemm(
    const float* __restrict__ Wo, const float* __restrict__ bo,
    float* __restrict__ out)
{
    extern __shared__ __align__(16) __nv_bfloat16 sm[];

    float C[4][4][4];
    #pragma unroll
    for (int i = 0; i < 4; i++)
        #pragma unroll
        for (int j = 0; j < 4; j++)
            #pragma unroll
            for (int e = 0; e < 4; e++) C[i][j][e] = 0.f;

    mma_gemm_body(g_attn, Wo, sm, C);

    const int tid = threadIdx.x;
    const int lane = tid & 31, w = tid >> 5;
    const int wm = (w >> 2) * 64, wn = (w & 3) * 32;
    const int bx = blockIdx.x, by = blockIdx.y;
    const int r = lane >> 2, c2 = (lane & 3) * 2;
    const int N = D_MODEL;

    #pragma unroll
    for (int i = 0; i < 4; i++)
        #pragma unroll
        for (int j = 0; j < 4; j++) {
            int gn = bx*BN + wn + j*8 + c2;
            float b0 = bo[gn], b1 = bo[gn+1];
            #pragma unroll
            for (int rr = 0; rr < 2; rr++) {
                int gm = by*BM + wm + i*16 + r + rr*8;
                float2 v;
                v.x = C[i][j][rr*2+0] + b0;
                v.y = C[i][j][rr*2+1] + b1;
                *(float2*)&out[(size_t)gm*N + gn] = v;
            }
        }
}

// ================= tensor-core flash attention =================
// CTA: 128 queries x one (b,h). 8 warps x m16 tiles. Key tiles of 64.
#define QSTR 72
#define KSTR 72
#define SM_QH 0
#define SM_QL (128*QSTR)              // 9216
#define SM_KH (2*128*QSTR)            // 18432
#define SM_KL (SM_KH + 64*KSTR)       // 23040
#define SM_VH (SM_KH + 2*64*KSTR)     // 27648
#define SM_VL (SM_KH + 3*64*KSTR)     // 32256
#define ATTN_SMEM_ELEMS (2*128*QSTR + 4*64*KSTR)  // 36864
#define ATTN_SMEM_BYTES (ATTN_SMEM_ELEMS*2)       // 73728

__global__ __launch_bounds__(256, 1) void attn_kernel()
{
    extern __shared__ __align__(16) __nv_bfloat16 sm[];

    const int b = blockIdx.z, h = blockIdx.y;
    const int tid = threadIdx.x;
    const int lane = tid & 31, w = tid >> 5;
    const int wm = w * 16;
    const int q0 = blockIdx.x * 128;
    const size_t headoff = ((size_t)(b*NUM_HEADS + h)) * SEQ * DK;

    // --- load Q hi/lo into smem (A layout, stride QSTR) ---
    {
        const uint4* GH = (const uint4*)(g_Qh + headoff + (size_t)q0*DK);
        const uint4* GL = (const uint4*)(g_Ql + headoff + (size_t)q0*DK);
        #pragma unroll
        for (int i = 0; i < 4; i++) {
            int g = tid + i*256;
            int row = g >> 3, ch = g & 7;
            *(uint4*)&sm[SM_QH + row*QSTR + ch*8] = GH[g];
            *(uint4*)&sm[SM_QL + row*QSTR + ch*8] = GL[g];
        }
    }

    // --- K/V tile prefetch state: 4 arrays x 512 uint4, 8 per thread ---
    const uint4* GKV[4] = {
        (const uint4*)(g_Kh + headoff), (const uint4*)(g_Kl + headoff),
        (const uint4*)(g_Vh + headoff), (const uint4*)(g_Vl + headoff) };
    const int smoff[4] = { SM_KH, SM_KL, SM_VH, SM_VL };

    uint4 pf[8];
    #pragma unroll
    for (int i = 0; i < 8; i++) {
        int rem = (i & 1)*256 + tid;
        pf[i] = GKV[i >> 1][rem];
    }

    // fragment lane addressing
    const int lrow  = lane & 15;               // A rows
    const int lkoff = (lane >> 4) << 3;        // A k-offset
    const int krow  = ((lane >> 4) & 1)*8 + (lane & 7);   // K (non-trans B) rows
    const int kcol  = ((lane >> 3) & 1)*8;                 // K k-offset
    const int tg = lane >> 3;
    const int vrow = (tg & 1)*8 + (lane & 7);  // V (trans B) rows (keys)
    const int vcol = (tg >> 1)*8;              // V n-offset (dk)

    float o[8][4];
    #pragma unroll
    for (int j = 0; j < 8; j++)
        #pragma unroll
        for (int e = 0; e < 4; e++) o[j][e] = 0.f;
    float m0 = -1e30f, m1 = -1e30f, l0 = 0.f, l1 = 0.f;

    for (int kt = 0; kt < SEQ/64; kt++) {
        // store prefetched tile
        #pragma unroll
        for (int i = 0; i < 8; i++) {
            int rem = (i & 1)*256 + tid;
            int row = rem >> 3, ch = rem & 7;
            *(uint4*)&sm[smoff[i >> 1] + row*KSTR + ch*8] = pf[i];
        }
        __syncthreads();

        if (kt + 1 < SEQ/64) {
            #pragma unroll
            for (int i = 0; i < 8; i++) {
                int rem = (i & 1)*256 + tid;
                pf[i] = GKV[i >> 1][(kt+1)*512 + rem];
            }
        }

        // ---- QK^T: scores 16x64 per warp ----
        float sc[8][4];
        #pragma unroll
        for (int j = 0; j < 8; j++)
            #pragma unroll
            for (int e = 0; e < 4; e++) sc[j][e] = 0.f;

        #pragma unroll
        for (int ks = 0; ks < 4; ks++) {
            const int kk = ks * 16;
            uint aH[4], aL[4];
            uint ad = smaddr(sm + SM_QH + (wm + lrow)*QSTR + kk + lkoff);
            ldsm4(ad, aH[0], aH[1], aH[2], aH[3]);
            ldsm4(ad + SM_QL*2, aL[0], aL[1], aL[2], aL[3]);
            #pragma unroll
            for (int g = 0; g < 4; g++) {
                uint bH[4], bL[4];
                uint bd = smaddr(sm + SM_KH + (g*16 + krow)*KSTR + kk + kcol);
                ldsm4(bd, bH[0], bH[1], bH[2], bH[3]);
                ldsm4(bd + (SM_KL - SM_KH)*2, bL[0], bL[1], bL[2], bL[3]);
                mma16816(sc[2*g],   aH, bH[0], bH[1]);
                mma16816(sc[2*g],   aH, bL[0], bL[1]);
                mma16816(sc[2*g],   aL, bH[0], bH[1]);
                mma16816(sc[2*g+1], aH, bH[2], bH[3]);
                mma16816(sc[2*g+1], aH, bL[2], bL[3]);
                mma16816(sc[2*g+1], aL, bH[2], bH[3]);
            }
        }

        // ---- online softmax (log2 domain) ----
        float tm0 = m0, tm1 = m1;
        #pragma unroll
        for (int j = 0; j < 8; j++) {
            tm0 = fmaxf(tm0, fmaxf(sc[j][0], sc[j][1]));
            tm1 = fmaxf(tm1, fmaxf(sc[j][2], sc[j][3]));
        }
        tm0 = fmaxf(tm0, __shfl_xor_sync(0xffffffffu, tm0, 1));
        tm0 = fmaxf(tm0, __shfl_xor_sync(0xffffffffu, tm0, 2));
        tm1 = fmaxf(tm1, __shfl_xor_sync(0xffffffffu, tm1, 1));
        tm1 = fmaxf(tm1, __shfl_xor_sync(0xffffffffu, tm1, 2));
        float corr0 = ex2(m0 - tm0), corr1 = ex2(m1 - tm1);
        m0 = tm0; m1 = tm1;
        l0 *= corr0; l1 *= corr1;
        #pragma unroll
        for (int j = 0; j < 8; j++) {
            o[j][0] *= corr0; o[j][1] *= corr0;
            o[j][2] *= corr1; o[j][3] *= corr1;
        }

        // ---- P conversion + PV, per k-step (16 keys) ----
        #pragma unroll
        for (int s = 0; s < 4; s++) {
            uint pH[4], pL[4];
            #pragma unroll
            for (int half = 0; half < 2; half++) {
                const int j = 2*s + half;
                float p0 = ex2(sc[j][0] - m0);
                float p1 = ex2(sc[j][1] - m0);
                float p2 = ex2(sc[j][2] - m1);
                float p3 = ex2(sc[j][3] - m1);
                l0 += p0 + p1;
                l1 += p2 + p3;
                split2(p0, p1, pH[half*2+0], pL[half*2+0]);
                split2(p2, p3, pH[half*2+1], pL[half*2+1]);
            }
            #pragma unroll
            for (int g = 0; g < 4; g++) {
                uint vH[4], vL[4];
                uint vd = smaddr(sm + SM_VH + (s*16 + vrow)*KSTR + g*16 + vcol);
                ldsm4t(vd, vH[0], vH[1], vH[2], vH[3]);
                ldsm4t(vd + (SM_VL - SM_VH)*2, vL[0], vL[1], vL[2], vL[3]);
                mma16816(o[2*g],   pH, vH[0], vH[1]);
                mma16816(o[2*g],   pH, vL[0], vL[1]);
                mma16816(o[2*g],   pL, vH[0], vH[1]);
                mma16816(o[2*g+1], pH, vH[2], vH[3]);
                mma16816(o[2*g+1], pH, vL[2], vL[3]);
                mma16816(o[2*g+1], pL, vH[2], vH[3]);
            }
        }
        __syncthreads();
    }

    // row sums across the 4-lane groups
    l0 += __shfl_xor_sync(0xffffffffu, l0, 1);
    l0 += __shfl_xor_sync(0xffffffffu, l0, 2);
    l1 += __shfl_xor_sync(0xffffffffu, l1, 1);
    l1 += __shfl_xor_sync(0xffffffffu, l1, 2);
    float inv0 = 1.f / l0, inv1 = 1.f / l1;

    const int r = lane >> 2, c2l = (lane & 3) * 2;
    size_t row0 = ((size_t)(b*SEQ + q0 + wm + r))*D_MODEL + h*DK;
    size_t row1 = row0 + (size_t)8*D_MODEL;
    #pragma unroll
    for (int j = 0; j < 8; j++) {
        float2 v0, v1;
        v0.x = o[j][0]*inv0; v0.y = o[j][1]*inv0;
        v1.x = o[j][2]*inv1; v1.y = o[j][3]*inv1;
        *(float2*)&g_attn[row0 + j*8 + c2l] = v0;
        *(float2*)&g_attn[row1 + j*8 + c2l] = v1;
    }
}

extern "C" void kernel_launch(void* const* d_in, const int* in_sizes, int n_in,
                              void* d_out, int out_size)
{
    const float* X  = (const float*)d_in[0];
    const float* Wq = (const float*)d_in[1];
    const float* bq = (const float*)d_in[2];
    const float* Wk = (const float*)d_in[3];
    const float* bk = (const float*)d_in[4];
    const float* Wv = (const float*)d_in[5];
    const float* bv = (const float*)d_in[6];
    const float* Wo = (const float*)d_in[7];
    const float* bo = (const float*)d_in[8];
    float* out = (float*)d_out;

    static int configured = 0;
    if (!configured) {
        cudaFuncSetAttribute(qkv_gemm, cudaFuncAttributeMaxDynamicSharedMemorySize, GEMM_SMEM_BYTES);
        cudaFuncSetAttribute(out_gemm, cudaFuncAttributeMaxDynamicSharedMemorySize, GEMM_SMEM_BYTES);
        cudaFuncSetAttribute(attn_kernel, cudaFuncAttributeMaxDynamicSharedMemorySize, ATTN_SMEM_BYTES);
        configured = 1;
    }

    dim3 gq(D_MODEL/BN, M_TOT/BM, 3);
    qkv_gemm<<<gq, 256, GEMM_SMEM_BYTES>>>(X, Wq, bq, Wk, bk, Wv, bv);

    dim3 ga(SEQ/128, NUM_HEADS, BATCH);
    attn_kernel<<<ga, 256, ATTN_SMEM_BYTES>>>();

    dim3 go(D_MODEL/BN, M_TOT/BM);
    out_gemm<<<go, 256, GEMM_SMEM_BYTES>>>(Wo, bo, out);
}

// round 5
// speedup vs baseline: 4.4549x; 1.1019x over previous
#include <cuda_runtime.h>
#include <cuda_bf16.h>

#define D_MODEL 1024
#define NUM_HEADS 16
#define BATCH 2
#define SEQ 2048
#define DK 64
#define M_TOT (BATCH*SEQ)   // 4096

typedef unsigned int uint;

// log2(e)/sqrt(dk) folded into stored Q
#define SCALE_Q 0.1803368801111244f

#define XN ((size_t)M_TOT*D_MODEL)    // 4M elements
#define WN ((size_t)D_MODEL*D_MODEL)  // 1M elements
#define QKV_ELEMS ((size_t)BATCH*NUM_HEADS*SEQ*DK)

// ---- pre-split bf16 hi/lo globals ----
__device__ __nv_bfloat16 g_Xh[XN],  g_Xl[XN];
__device__ __nv_bfloat16 g_Wh[4*WN], g_Wl[4*WN];  // Wq,Wk,Wv,Wo
__device__ __nv_bfloat16 g_Qh[QKV_ELEMS], g_Ql[QKV_ELEMS];
__device__ __nv_bfloat16 g_Kh[QKV_ELEMS], g_Kl[QKV_ELEMS];
__device__ __nv_bfloat16 g_Vh[QKV_ELEMS], g_Vl[QKV_ELEMS];
__device__ __nv_bfloat16 g_Ah[XN],  g_Al[XN];      // attention output (split)

__device__ __forceinline__ uint smaddr(const void* p) {
    return (uint)__cvta_generic_to_shared(p);
}
__device__ __forceinline__ void ldsm4(uint addr, uint& r0, uint& r1, uint& r2, uint& r3) {
    asm volatile("ldmatrix.sync.aligned.m8n8.x4.shared.b16 {%0,%1,%2,%3}, [%4];"
        : "=r"(r0), "=r"(r1), "=r"(r2), "=r"(r3) : "r"(addr));
}
__device__ __forceinline__ void ldsm4t(uint addr, uint& r0, uint& r1, uint& r2, uint& r3) {
    asm volatile("ldmatrix.sync.aligned.m8n8.x4.trans.shared.b16 {%0,%1,%2,%3}, [%4];"
        : "=r"(r0), "=r"(r1), "=r"(r2), "=r"(r3) : "r"(addr));
}
__device__ __forceinline__ void mma16816(float c[4], const uint a[4], uint b0, uint b1) {
    asm volatile("mma.sync.aligned.m16n8k16.row.col.f32.bf16.bf16.f32 "
        "{%0,%1,%2,%3}, {%4,%5,%6,%7}, {%8,%9}, {%0,%1,%2,%3};"
        : "+f"(c[0]), "+f"(c[1]), "+f"(c[2]), "+f"(c[3])
        : "r"(a[0]), "r"(a[1]), "r"(a[2]), "r"(a[3]), "r"(b0), "r"(b1));
}
__device__ __forceinline__ float ex2(float x) {
    float y; asm("ex2.approx.f32 %0, %1;" : "=f"(y) : "f"(x)); return y;
}
__device__ __forceinline__ void split2(float x, float y, uint& hv, uint& lv) {
    __nv_bfloat162 h = __floats2bfloat162_rn(x, y);
    float2 hf = __bfloat1622float2(h);
    __nv_bfloat162 l = __floats2bfloat162_rn(x - hf.x, y - hf.y);
    hv = *(uint*)&h; lv = *(uint*)&l;
}
__device__ __forceinline__ void cpa16(uint dst, const void* src) {
    asm volatile("cp.async.cg.shared.global [%0], [%1], 16;" :: "r"(dst), "l"(src));
}

// ================= pre-pass: split X + all W into bf16 hi/lo =================
__global__ __launch_bounds__(256) void split_pre(
    const float* __restrict__ X,
    const float* __restrict__ Wq, const float* __restrict__ Wk,
    const float* __restrict__ Wv, const float* __restrict__ Wo)
{
    size_t pi = ((size_t)blockIdx.x*256 + threadIdx.x)*2;
    const float* src; __nv_bfloat16 *dh, *dl; size_t off;
    if (pi < XN) { src = X; off = pi; dh = g_Xh; dl = g_Xl; }
    else {
        size_t r = pi - XN;
        int w = (int)(r >> 20);
        off = r & (WN - 1);
        src = (w == 0) ? Wq : (w == 1) ? Wk : (w == 2) ? Wv : Wo;
        dh = g_Wh + (size_t)w*WN; dl = g_Wl + (size_t)w*WN;
    }
    float2 v = *(const float2*)&src[off];
    uint hv, lv; split2(v.x, v.y, hv, lv);
    *(uint*)&dh[off] = hv;
    *(uint*)&dl[off] = lv;
}

// ================= tensor-core GEMM (split-bf16, 3-pass, cp.async) =================
#define BM 128
#define BN 128
#define BK 32
#define ASTR 40
#define BSTR 136
#define AH_OFF 0
#define AL_OFF (BM*ASTR)                  // 5120
#define BH_OFF (2*BM*ASTR)                // 10240
#define BL_OFF (2*BM*ASTR + BK*BSTR)      // 14592
#define BUF_ELEMS (2*BM*ASTR + 2*BK*BSTR) // 18944
#define BUF_BYTES (BUF_ELEMS*2)           // 37888
#define GEMM_SMEM_BYTES (2*BUF_BYTES)     // 75776

__device__ __forceinline__ void gemm_load_tile(
    uint S, int tid, int bx, int by, int k0,
    const __nv_bfloat16* __restrict__ Ah, const __nv_bfloat16* __restrict__ Al,
    const __nv_bfloat16* __restrict__ Bh, const __nv_bfloat16* __restrict__ Bl)
{
    const int K = D_MODEL, N = D_MODEL;
    #pragma unroll
    for (int t = 0; t < 2; t++) {
        int c = tid + t*256;
        int row = c >> 2, off = (c & 3)*8;
        size_t g = (size_t)(by*BM + row)*K + k0 + off;
        cpa16(S + (AH_OFF + row*ASTR + off)*2, Ah + g);
        cpa16(S + (AL_OFF + row*ASTR + off)*2, Al + g);
    }
    #pragma unroll
    for (int t = 0; t < 2; t++) {
        int c = tid + t*256;
        int row = c >> 4, col = (c & 15)*8;
        size_t g = (size_t)(k0 + row)*N + bx*BN + col;
        cpa16(S + (BH_OFF + row*BSTR + col)*2, Bh + g);
        cpa16(S + (BL_OFF + row*BSTR + col)*2, Bl + g);
    }
    asm volatile("cp.async.commit_group;" ::: "memory");
}

__device__ __forceinline__ void mma_gemm_body(
    const __nv_bfloat16* __restrict__ Ah, const __nv_bfloat16* __restrict__ Al,
    const __nv_bfloat16* __restrict__ Bh, const __nv_bfloat16* __restrict__ Bl,
    __nv_bfloat16* sm, float C[4][4][4])
{
    const int K = D_MODEL;
    const int tid = threadIdx.x;
    const int lane = tid & 31, w = tid >> 5;
    const int wm = (w >> 2)*64, wn = (w & 3)*32;
    const int bx = blockIdx.x, by = blockIdx.y;

    const int lrow = lane & 15;
    const int lkoff = (lane >> 4) << 3;
    const int tg = lane >> 3;
    const int b_lrow = (tg & 1)*8 + (lane & 7);
    const int b_lcol = (tg >> 1)*8;

    const uint S0 = smaddr(sm);

    gemm_load_tile(S0, tid, bx, by, 0, Ah, Al, Bh, Bl);

    int buf = 0;
    for (int k0 = 0; k0 < K; k0 += BK) {
        bool more = (k0 + BK < K);
        if (more)
            gemm_load_tile(S0 + (buf^1)*BUF_BYTES, tid, bx, by, k0 + BK, Ah, Al, Bh, Bl);

        if (more) asm volatile("cp.async.wait_group 1;" ::: "memory");
        else      asm volatile("cp.async.wait_group 0;" ::: "memory");
        __syncthreads();

        const uint Sb = S0 + buf*BUF_BYTES;
        #pragma unroll
        for (int ks = 0; ks < 2; ks++) {
            const int kk = ks*16;
            uint ah[4][4], al[4][4];
            #pragma unroll
            for (int i = 0; i < 4; i++) {
                uint ad = Sb + (AH_OFF + (wm + i*16 + lrow)*ASTR + kk + lkoff)*2;
                ldsm4(ad, ah[i][0], ah[i][1], ah[i][2], ah[i][3]);
                ldsm4(ad + AL_OFF*2, al[i][0], al[i][1], al[i][2], al[i][3]);
            }
            #pragma unroll
            for (int p = 0; p < 2; p++) {
                uint bh[4], bl[4];
                uint bd = Sb + (BH_OFF + (kk + b_lrow)*BSTR + wn + p*16 + b_lcol)*2;
                ldsm4t(bd, bh[0], bh[1], bh[2], bh[3]);
                ldsm4t(bd + (BL_OFF - BH_OFF)*2, bl[0], bl[1], bl[2], bl[3]);
                #pragma unroll
                for (int i = 0; i < 4; i++) {
                    mma16816(C[i][2*p],   ah[i], bh[0], bh[1]);
                    mma16816(C[i][2*p],   ah[i], bl[0], bl[1]);
                    mma16816(C[i][2*p],   al[i], bh[0], bh[1]);
                    mma16816(C[i][2*p+1], ah[i], bh[2], bh[3]);
                    mma16816(C[i][2*p+1], ah[i], bl[2], bl[3]);
                    mma16816(C[i][2*p+1], al[i], bh[2], bh[3]);
                }
            }
        }
        __syncthreads();
        buf ^= 1;
    }
}

// QKV projection -> split bf16 head-major [B,H,S,dk]; Q pre-scaled
__global__ __launch_bounds__(256, 2) void qkv_gemm(
    const float* __restrict__ bq, const float* __restrict__ bk,
    const float* __restrict__ bv)
{
    extern __shared__ __align__(16) __nv_bfloat16 sm[];

    const float* bias;
    __nv_bfloat16 *dsth, *dstl;
    float scale;
    const int z = blockIdx.z;
    if (z == 0)      { bias = bq; dsth = g_Qh; dstl = g_Ql; scale = SCALE_Q; }
    else if (z == 1) { bias = bk; dsth = g_Kh; dstl = g_Kl; scale = 1.f; }
    else             { bias = bv; dsth = g_Vh; dstl = g_Vl; scale = 1.f; }

    float C[4][4][4];
    #pragma unroll
    for (int i = 0; i < 4; i++)
        #pragma unroll
        for (int j = 0; j < 4; j++)
            #pragma unroll
            for (int e = 0; e < 4; e++) C[i][j][e] = 0.f;

    mma_gemm_body(g_Xh, g_Xl, g_Wh + (size_t)z*WN, g_Wl + (size_t)z*WN, sm, C);

    const int tid = threadIdx.x;
    const int lane = tid & 31, w = tid >> 5;
    const int wm = (w >> 2)*64, wn = (w & 3)*32;
    const int bx = blockIdx.x, by = blockIdx.y;
    const int r = lane >> 2, c2 = (lane & 3)*2;

    #pragma unroll
    for (int i = 0; i < 4; i++)
        #pragma unroll
        for (int j = 0; j < 4; j++) {
            int gn = bx*BN + wn + j*8 + c2;
            int h = gn >> 6, d = gn & 63;
            float b0 = bias[gn], b1 = bias[gn+1];
            #pragma unroll
            for (int rr = 0; rr < 2; rr++) {
                int gm = by*BM + wm + i*16 + r + rr*8;
                int bat = gm >> 11, s = gm & 2047;
                float vx = (C[i][j][rr*2+0] + b0) * scale;
                float vy = (C[i][j][rr*2+1] + b1) * scale;
                uint hv, lv;
                split2(vx, vy, hv, lv);
                size_t idx = ((((size_t)bat*NUM_HEADS + h)*SEQ + s) << 6) + d;
                *(uint*)&dsth[idx] = hv;
                *(uint*)&dstl[idx] = lv;
            }
        }
}

// Output projection: out = attn @ Wo + bo (A pre-split by attention epilogue)
__global__ __launch_bounds__(256, 2) void out_gemm(
    const float* __restrict__ bo, float* __restrict__ out)
{
    extern __shared__ __align__(16) __nv_bfloat16 sm[];

    float C[4][4][4];
    #pragma unroll
    for (int i = 0; i < 4; i++)
        #pragma unroll
        for (int j = 0; j < 4; j++)
            #pragma unroll
            for (int e = 0; e < 4; e++) C[i][j][e] = 0.f;

    mma_gemm_body(g_Ah, g_Al, g_Wh + (size_t)3*WN, g_Wl + (size_t)3*WN, sm, C);

    const int tid = threadIdx.x;
    const int lane = tid & 31, w = tid >> 5;
    const int wm = (w >> 2)*64, wn = (w & 3)*32;
    const int bx = blockIdx.x, by = blockIdx.y;
    const int r = lane >> 2, c2 = (lane & 3)*2;
    const int N = D_MODEL;

    #pragma unroll
    for (int i = 0; i < 4; i++)
        #pragma unroll
        for (int j = 0; j < 4; j++) {
            int gn = bx*BN + wn + j*8 + c2;
            float b0 = bo[gn], b1 = bo[gn+1];
            #pragma unroll
            for (int rr = 0; rr < 2; rr++) {
                int gm = by*BM + wm + i*16 + r + rr*8;
                float2 v;
                v.x = C[i][j][rr*2+0] + b0;
                v.y = C[i][j][rr*2+1] + b1;
                *(float2*)&out[(size_t)gm*N + gn] = v;
            }
        }
}

// ================= tensor-core flash attention =================
#define QSTR 72
#define KSTR 72
#define SM_QH 0
#define SM_QL (128*QSTR)
#define SM_KH (2*128*QSTR)
#define SM_KL (SM_KH + 64*KSTR)
#define SM_VH (SM_KH + 2*64*KSTR)
#define SM_VL (SM_KH + 3*64*KSTR)
#define ATTN_SMEM_ELEMS (2*128*QSTR + 4*64*KSTR)
#define ATTN_SMEM_BYTES (ATTN_SMEM_ELEMS*2)

__global__ __launch_bounds__(256, 1) void attn_kernel()
{
    extern __shared__ __align__(16) __nv_bfloat16 sm[];

    const int b = blockIdx.z, h = blockIdx.y;
    const int tid = threadIdx.x;
    const int lane = tid & 31, w = tid >> 5;
    const int wm = w * 16;
    const int q0 = blockIdx.x * 128;
    const size_t headoff = ((size_t)(b*NUM_HEADS + h)) * SEQ * DK;

    {
        const uint4* GH = (const uint4*)(g_Qh + headoff + (size_t)q0*DK);
        const uint4* GL = (const uint4*)(g_Ql + headoff + (size_t)q0*DK);
        #pragma unroll
        for (int i = 0; i < 4; i++) {
            int g = tid + i*256;
            int row = g >> 3, ch = g & 7;
            *(uint4*)&sm[SM_QH + row*QSTR + ch*8] = GH[g];
            *(uint4*)&sm[SM_QL + row*QSTR + ch*8] = GL[g];
        }
    }

    const uint4* GKV[4] = {
        (const uint4*)(g_Kh + headoff), (const uint4*)(g_Kl + headoff),
        (const uint4*)(g_Vh + headoff), (const uint4*)(g_Vl + headoff) };
    const int smoff[4] = { SM_KH, SM_KL, SM_VH, SM_VL };

    uint4 pf[8];
    #pragma unroll
    for (int i = 0; i < 8; i++) {
        int rem = (i & 1)*256 + tid;
        pf[i] = GKV[i >> 1][rem];
    }

    const int lrow  = lane & 15;
    const int lkoff = (lane >> 4) << 3;
    const int krow  = ((lane >> 4) & 1)*8 + (lane & 7);
    const int kcol  = ((lane >> 3) & 1)*8;
    const int tg = lane >> 3;
    const int vrow = (tg & 1)*8 + (lane & 7);
    const int vcol = (tg >> 1)*8;

    float o[8][4];
    #pragma unroll
    for (int j = 0; j < 8; j++)
        #pragma unroll
        for (int e = 0; e < 4; e++) o[j][e] = 0.f;
    float m0 = -1e30f, m1 = -1e30f, l0 = 0.f, l1 = 0.f;

    for (int kt = 0; kt < SEQ/64; kt++) {
        #pragma unroll
        for (int i = 0; i < 8; i++) {
            int rem = (i & 1)*256 + tid;
            int row = rem >> 3, ch = rem & 7;
            *(uint4*)&sm[smoff[i >> 1] + row*KSTR + ch*8] = pf[i];
        }
        __syncthreads();

        if (kt + 1 < SEQ/64) {
            #pragma unroll
            for (int i = 0; i < 8; i++) {
                int rem = (i & 1)*256 + tid;
                pf[i] = GKV[i >> 1][(kt+1)*512 + rem];
            }
        }

        float sc[8][4];
        #pragma unroll
        for (int j = 0; j < 8; j++)
            #pragma unroll
            for (int e = 0; e < 4; e++) sc[j][e] = 0.f;

        #pragma unroll
        for (int ks = 0; ks < 4; ks++) {
            const int kk = ks * 16;
            uint aH[4], aL[4];
            uint ad = smaddr(sm + SM_QH + (wm + lrow)*QSTR + kk + lkoff);
            ldsm4(ad, aH[0], aH[1], aH[2], aH[3]);
            ldsm4(ad + SM_QL*2, aL[0], aL[1], aL[2], aL[3]);
            #pragma unroll
            for (int g = 0; g < 4; g++) {
                uint bH[4], bL[4];
                uint bd = smaddr(sm + SM_KH + (g*16 + krow)*KSTR + kk + kcol);
                ldsm4(bd, bH[0], bH[1], bH[2], bH[3]);
                ldsm4(bd + (SM_KL - SM_KH)*2, bL[0], bL[1], bL[2], bL[3]);
                mma16816(sc[2*g],   aH, bH[0], bH[1]);
                mma16816(sc[2*g],   aH, bL[0], bL[1]);
                mma16816(sc[2*g],   aL, bH[0], bH[1]);
                mma16816(sc[2*g+1], aH, bH[2], bH[3]);
                mma16816(sc[2*g+1], aH, bL[2], bL[3]);
                mma16816(sc[2*g+1], aL, bH[2], bH[3]);
            }
        }

        float tm0 = m0, tm1 = m1;
        #pragma unroll
        for (int j = 0; j < 8; j++) {
            tm0 = fmaxf(tm0, fmaxf(sc[j][0], sc[j][1]));
            tm1 = fmaxf(tm1, fmaxf(sc[j][2], sc[j][3]));
        }
        tm0 = fmaxf(tm0, __shfl_xor_sync(0xffffffffu, tm0, 1));
        tm0 = fmaxf(tm0, __shfl_xor_sync(0xffffffffu, tm0, 2));
        tm1 = fmaxf(tm1, __shfl_xor_sync(0xffffffffu, tm1, 1));
        tm1 = fmaxf(tm1, __shfl_xor_sync(0xffffffffu, tm1, 2));
        float corr0 = ex2(m0 - tm0), corr1 = ex2(m1 - tm1);
        m0 = tm0; m1 = tm1;
        l0 *= corr0; l1 *= corr1;
        #pragma unroll
        for (int j = 0; j < 8; j++) {
            o[j][0] *= corr0; o[j][1] *= corr0;
            o[j][2] *= corr1; o[j][3] *= corr1;
        }

        #pragma unroll
        for (int s = 0; s < 4; s++) {
            uint pH[4], pL[4];
            #pragma unroll
            for (int half = 0; half < 2; half++) {
                const int j = 2*s + half;
                float p0 = ex2(sc[j][0] - m0);
                float p1 = ex2(sc[j][1] - m0);
                float p2 = ex2(sc[j][2] - m1);
                float p3 = ex2(sc[j][3] - m1);
                l0 += p0 + p1;
                l1 += p2 + p3;
                split2(p0, p1, pH[half*2+0], pL[half*2+0]);
                split2(p2, p3, pH[half*2+1], pL[half*2+1]);
            }
            #pragma unroll
            for (int g = 0; g < 4; g++) {
                uint vH[4], vL[4];
                uint vd = smaddr(sm + SM_VH + (s*16 + vrow)*KSTR + g*16 + vcol);
                ldsm4t(vd, vH[0], vH[1], vH[2], vH[3]);
                ldsm4t(vd + (SM_VL - SM_VH)*2, vL[0], vL[1], vL[2], vL[3]);
                mma16816(o[2*g],   pH, vH[0], vH[1]);
                mma16816(o[2*g],   pH, vL[0], vL[1]);
                mma16816(o[2*g],   pL, vH[0], vH[1]);
                mma16816(o[2*g+1], pH, vH[2], vH[3]);
                mma16816(o[2*g+1], pH, vL[2], vL[3]);
                mma16816(o[2*g+1], pL, vH[2], vH[3]);
            }
        }
        __syncthreads();
    }

    l0 += __shfl_xor_sync(0xffffffffu, l0, 1);
    l0 += __shfl_xor_sync(0xffffffffu, l0, 2);
    l1 += __shfl_xor_sync(0xffffffffu, l1, 1);
    l1 += __shfl_xor_sync(0xffffffffu, l1, 2);
    float inv0 = 1.f / l0, inv1 = 1.f / l1;

    const int r = lane >> 2, c2l = (lane & 3) * 2;
    size_t row0 = ((size_t)(b*SEQ + q0 + wm + r))*D_MODEL + h*DK;
    size_t row1 = row0 + (size_t)8*D_MODEL;
    #pragma unroll
    for (int j = 0; j < 8; j++) {
        uint h0, l0u, h1, l1u;
        split2(o[j][0]*inv0, o[j][1]*inv0, h0, l0u);
        split2(o[j][2]*inv1, o[j][3]*inv1, h1, l1u);
        *(uint*)&g_Ah[row0 + j*8 + c2l] = h0;
        *(uint*)&g_Al[row0 + j*8 + c2l] = l0u;
        *(uint*)&g_Ah[row1 + j*8 + c2l] = h1;
        *(uint*)&g_Al[row1 + j*8 + c2l] = l1u;
    }
}

extern "C" void kernel_launch(void* const* d_in, const int* in_sizes, int n_in,
                              void* d_out, int out_size)
{
    const float* X  = (const float*)d_in[0];
    const float* Wq = (const float*)d_in[1];
    const float* bq = (const float*)d_in[2];
    const float* Wk = (const float*)d_in[3];
    const float* bk = (const float*)d_in[4];
    const float* Wv = (const float*)d_in[5];
    const float* bv = (const float*)d_in[6];
    const float* Wo = (const float*)d_in[7];
    const float* bo = (const float*)d_in[8];
    float* out = (float*)d_out;

    static int configured = 0;
    if (!configured) {
        cudaFuncSetAttribute(qkv_gemm, cudaFuncAttributeMaxDynamicSharedMemorySize, GEMM_SMEM_BYTES);
        cudaFuncSetAttribute(out_gemm, cudaFuncAttributeMaxDynamicSharedMemorySize, GEMM_SMEM_BYTES);
        cudaFuncSetAttribute(attn_kernel, cudaFuncAttributeMaxDynamicSharedMemorySize, ATTN_SMEM_BYTES);
        configured = 1;
    }

    // pre-split X and all W (8M elements, 2 per thread)
    split_pre<<<16384, 256>>>(X, Wq, Wk, Wv, Wo);

    dim3 gq(D_MODEL/BN, M_TOT/BM, 3);
    qkv_gemm<<<gq, 256, GEMM_SMEM_BYTES>>>(bq, bk, bv);

    dim3 ga(SEQ/128, NUM_HEADS, BATCH);
    attn_kernel<<<ga, 256, ATTN_SMEM_BYTES>>>();

    dim3 go(D_MODEL/BN, M_TOT/BM);
    out_gemm<<<go, 256, GEMM_SMEM_BYTES>>>(bo, out);
}